// round 1
// baseline (speedup 1.0000x reference)
#include <cuda_runtime.h>
#include <math.h>

// Problem constants (fixed by setup_inputs)
#define T_STEPS 512
#define BATCH   64
#define HID     512
#define GDIM    2048   // 4*H
#define DDIM    512

// ---- scratch (device globals: allocation-free rule) ----
__device__ float g_xproj[(size_t)T_STEPS * BATCH * GDIM];  // 268 MB
__device__ float g_h[BATCH * HID];
__device__ unsigned int g_bar_count = 0;
__device__ unsigned int g_bar_gen   = 0;

__device__ __forceinline__ float sigmoidf_(float x) { return 1.0f / (1.0f + expf(-x)); }

// =====================================================================
// Kernel 1: x_proj[M=T*B, N=4H] = X[M, D] @ Wx[D, 4H] + b
// Classic 128x128x8 tiled SGEMM, 256 threads, 8x8 microtile.
// =====================================================================
#define BM 128
#define BN 128
#define BKK 8

__global__ __launch_bounds__(256) void k_xproj(const float* __restrict__ A,
                                               const float* __restrict__ B,
                                               const float* __restrict__ bias) {
    __shared__ float As[BKK][BM];
    __shared__ float Bs[BKK][BN];
    const int Kd = DDIM, Nd = GDIM;
    const int brow = blockIdx.y * BM;
    const int bcol = blockIdx.x * BN;
    const int tid = threadIdx.x;
    const int tx = tid & 15, ty = tid >> 4;

    float acc[8][8];
#pragma unroll
    for (int i = 0; i < 8; i++)
#pragma unroll
        for (int j = 0; j < 8; j++) acc[i][j] = 0.0f;

    const int a_row = tid >> 1, a_k = (tid & 1) << 2;
    const int b_k = tid >> 5,  b_n = (tid & 31) << 2;
    const float* Ap = A + (size_t)brow * Kd;
    const float* Bp = B + bcol;

    for (int k0 = 0; k0 < Kd; k0 += BKK) {
        float4 av = *(const float4*)(Ap + (size_t)a_row * Kd + k0 + a_k);
        As[a_k + 0][a_row] = av.x;
        As[a_k + 1][a_row] = av.y;
        As[a_k + 2][a_row] = av.z;
        As[a_k + 3][a_row] = av.w;
        float4 bv = *(const float4*)(Bp + (size_t)(k0 + b_k) * Nd + b_n);
        *(float4*)&Bs[b_k][b_n] = bv;
        __syncthreads();

#pragma unroll
        for (int kk = 0; kk < BKK; kk++) {
            float4 a0 = *(const float4*)&As[kk][ty * 8];
            float4 a1 = *(const float4*)&As[kk][ty * 8 + 4];
            float4 b0 = *(const float4*)&Bs[kk][tx * 8];
            float4 b1 = *(const float4*)&Bs[kk][tx * 8 + 4];
            float ar[8] = {a0.x, a0.y, a0.z, a0.w, a1.x, a1.y, a1.z, a1.w};
            float br[8] = {b0.x, b0.y, b0.z, b0.w, b1.x, b1.y, b1.z, b1.w};
#pragma unroll
            for (int i = 0; i < 8; i++)
#pragma unroll
                for (int j = 0; j < 8; j++)
                    acc[i][j] += ar[i] * br[j];
        }
        __syncthreads();
    }

#pragma unroll
    for (int i = 0; i < 8; i++) {
        size_t r = (size_t)(brow + ty * 8 + i);
#pragma unroll
        for (int j = 0; j < 8; j += 4) {
            int cidx = bcol + tx * 8 + j;
            float4 o;
            o.x = acc[i][j + 0] + bias[cidx + 0];
            o.y = acc[i][j + 1] + bias[cidx + 1];
            o.z = acc[i][j + 2] + bias[cidx + 2];
            o.w = acc[i][j + 3] + bias[cidx + 3];
            *(float4*)(g_xproj + r * Nd + cidx) = o;
        }
    }
}

// =====================================================================
// Kernel 2: persistent masked-LSTM recurrence.
// 128 CTAs (<=148 SMs, 1 CTA/SM via big smem => co-residency guaranteed),
// software grid barrier per timestep. Each CTA owns 4 h-columns:
//   - Wh slice [512 x 16] resident in smem (transposed) for all 512 steps
//   - c state in registers for the whole kernel
//   - h broadcast via L2 (g_h) once per step
// =====================================================================
#define NCTA 128
#define NTHR 256
#define HSTR 516   // h_s row stride (pad: bank-safe, float4-aligned)
#define WSTR 516   // wh_s row stride

#define SMEM2 ((16 * WSTR + BATCH * HSTR + BATCH + BATCH * 17) * 4)

__global__ __launch_bounds__(NTHR, 1) void k_rnn(const float* __restrict__ h0,
                                                 const float* __restrict__ c0,
                                                 const float* __restrict__ mask,
                                                 const float* __restrict__ Wh,
                                                 float* __restrict__ out) {
    extern __shared__ float sm[];
    float* wh_s   = sm;                        // [16][WSTR]
    float* h_s    = sm + 16 * WSTR;            // [64][HSTR]
    float* keep_s = h_s + BATCH * HSTR;        // [64]
    float* gates_s = keep_s + BATCH;           // [64][17]

    const int tid = threadIdx.x;
    const int cta = blockIdx.x;
    const int hc0 = cta * 4;                   // 4 h-columns per CTA

    // Load Wh slice, transposed: wh_s[c][k] = Wh[k][gate(c)*512 + hc0 + j(c)]
    for (int idx = tid; idx < 16 * 512; idx += NTHR) {
        int c = idx >> 9;
        int k = idx & 511;
        int gcol = (c >> 2) * HID + hc0 + (c & 3);
        wh_s[c * WSTR + k] = Wh[(size_t)k * GDIM + gcol];
    }

    // Update-phase mapping: one (batch, hcol) element per thread
    const int ub = tid >> 2;
    const int uj = tid & 3;
    float c_reg = c0[ub * HID + hc0 + uj];
    float h_last = 0.0f;

    // GEMM-phase mapping: 4 batch rows x 1 gate column per thread
    const int col = tid & 15;
    const int rq  = tid >> 4;
    const int gcol_t = (col >> 2) * HID + hc0 + (col & 3);

    unsigned int bar_target = 0;
    if (tid == 0) bar_target = *((volatile unsigned int*)&g_bar_gen);

    __syncthreads();  // wh_s ready

    for (int t = 0; t < T_STEPS; t++) {
        // Prefetch x_proj contributions (DRAM latency overlaps h staging)
        const float* xp = g_xproj + ((size_t)t * BATCH + (rq << 2)) * GDIM + gcol_t;
        float acc0 = xp[0];
        float acc1 = xp[GDIM];
        float acc2 = xp[2 * GDIM];
        float acc3 = xp[3 * GDIM];

        if (tid < BATCH) keep_s[tid] = 1.0f - mask[t * BATCH + tid];
        __syncthreads();

        // Stage h (reset-masked) into smem
        const float4* hsrc = (const float4*)((t == 0) ? h0 : (const float*)g_h);
        for (int i = tid; i < (BATCH * HID) / 4; i += NTHR) {
            int row = i >> 7;          // / (512/4)
            int k4  = i & 127;
            float4 v = hsrc[i];
            float kp = keep_s[row];
            v.x *= kp; v.y *= kp; v.z *= kp; v.w *= kp;
            *((float4*)&h_s[row * HSTR + (k4 << 2)]) = v;
        }
        __syncthreads();

        // gates tile [64 x 16] += h_s[64 x 512] @ wh_s^T
        {
            const float* hr0 = &h_s[(rq * 4 + 0) * HSTR];
            const float* hr1 = &h_s[(rq * 4 + 1) * HSTR];
            const float* hr2 = &h_s[(rq * 4 + 2) * HSTR];
            const float* hr3 = &h_s[(rq * 4 + 3) * HSTR];
            const float* wc  = &wh_s[col * WSTR];
#pragma unroll 8
            for (int k = 0; k < HID; k += 4) {
                float4 w  = *(const float4*)(wc + k);
                float4 a  = *(const float4*)(hr0 + k);
                float4 b_ = *(const float4*)(hr1 + k);
                float4 c_ = *(const float4*)(hr2 + k);
                float4 d_ = *(const float4*)(hr3 + k);
                acc0 += a.x * w.x + a.y * w.y + a.z * w.z + a.w * w.w;
                acc1 += b_.x * w.x + b_.y * w.y + b_.z * w.z + b_.w * w.w;
                acc2 += c_.x * w.x + c_.y * w.y + c_.z * w.z + c_.w * w.w;
                acc3 += d_.x * w.x + d_.y * w.y + d_.z * w.z + d_.w * w.w;
            }
            gates_s[(rq * 4 + 0) * 17 + col] = acc0;
            gates_s[(rq * 4 + 1) * 17 + col] = acc1;
            gates_s[(rq * 4 + 2) * 17 + col] = acc2;
            gates_s[(rq * 4 + 3) * 17 + col] = acc3;
        }
        __syncthreads();

        // LSTM cell update (one element per thread, c in register)
        {
            float kp = keep_s[ub];
            float ig = gates_s[ub * 17 + 0 + uj];
            float fg = gates_s[ub * 17 + 4 + uj];
            float gg = gates_s[ub * 17 + 8 + uj];
            float og = gates_s[ub * 17 + 12 + uj];
            float cprev = c_reg * kp;
            float cn = sigmoidf_(fg) * cprev + sigmoidf_(ig) * tanhf(gg);
            float hn = sigmoidf_(og) * tanhf(cn);
            c_reg = cn;
            h_last = hn;
            int hcol = hc0 + uj;
            out[(size_t)t * BATCH * HID + ub * HID + hcol] = hn;
            g_h[ub * HID + hcol] = hn;
        }
        __threadfence();

        // ---- software grid barrier (generation-counter, replay-safe) ----
        __syncthreads();
        if (tid == 0) {
            bar_target += 1;
            unsigned int old = atomicAdd(&g_bar_count, 1);
            if (old == NCTA - 1) {
                atomicExch(&g_bar_count, 0);
                __threadfence();
                atomicAdd(&g_bar_gen, 1);
            } else {
                while ((int)(*((volatile unsigned int*)&g_bar_gen) - bar_target) < 0)
                    __nanosleep(32);
                __threadfence();
            }
        }
        __syncthreads();
    }

    // Finals
    float* hfin = out + (size_t)T_STEPS * BATCH * HID;
    float* cfin = hfin + BATCH * HID;
    hfin[ub * HID + hc0 + uj] = h_last;
    cfin[ub * HID + hc0 + uj] = c_reg;
}

// =====================================================================
extern "C" void kernel_launch(void* const* d_in, const int* in_sizes, int n_in,
                              void* d_out, int out_size) {
    (void)in_sizes; (void)n_in; (void)out_size;
    const float* x    = (const float*)d_in[0];
    const float* h0   = (const float*)d_in[1];
    const float* c0   = (const float*)d_in[2];
    const float* mask = (const float*)d_in[3];
    const float* Wx   = (const float*)d_in[4];
    const float* Wh   = (const float*)d_in[5];
    const float* b    = (const float*)d_in[6];
    float* out = (float*)d_out;

    // Kernel 1: big parallel input projection
    dim3 g1(GDIM / BN, (T_STEPS * BATCH) / BM);
    k_xproj<<<g1, 256>>>(x, Wx, b);

    // Kernel 2: persistent recurrence (needs >48KB dynamic smem opt-in)
    cudaFuncSetAttribute(k_rnn, cudaFuncAttributeMaxDynamicSharedMemorySize, SMEM2);
    k_rnn<<<NCTA, NTHR, SMEM2>>>(h0, c0, mask, Wh, out);
}

// round 2
// speedup vs baseline: 1.1833x; 1.1833x over previous
#include <cuda_runtime.h>
#include <math.h>

// Problem constants (fixed by setup_inputs)
#define T_STEPS 512
#define BATCH   64
#define HID     512
#define GDIM    2048   // 4*H
#define DDIM    512

typedef unsigned long long ull;

// ---- scratch (device globals: allocation-free rule) ----
__device__ float g_xproj[(size_t)T_STEPS * BATCH * GDIM];  // 268 MB
__device__ float g_h[BATCH * HID];
__device__ unsigned int g_bar_count = 0;
__device__ unsigned int g_bar_gen   = 0;

__device__ __forceinline__ float sigmoidf_(float x) { return 1.0f / (1.0f + expf(-x)); }

// Packed fp32x2 ops (Blackwell 2x FP32; only reachable via PTX)
#define FMA_X2(acc, a, b) asm("fma.rn.f32x2 %0,%1,%2,%0;" : "+l"(acc) : "l"(a), "l"(b))
#define ADD_X2(d, a, b)   asm("add.rn.f32x2 %0,%1,%2;"    : "=l"(d)  : "l"(a), "l"(b))
#define PACK_DUP(d, x)    asm("mov.b64 %0,{%1,%1};"        : "=l"(d)  : "f"(x))
#define PACK_XY(d, x, y)  asm("mov.b64 %0,{%1,%2};"        : "=l"(d)  : "f"(x), "f"(y))
#define UNPACK(lo, hi, v) asm("mov.b64 {%0,%1},%2;"        : "=f"(lo), "=f"(hi) : "l"(v))

// =====================================================================
// Kernel 1: x_proj[M=T*B, N=4H] = X[M, D] @ Wx[D, 4H] + b
// 128x128x8 tiled, 256 threads, 8x8 microtile, packed f32x2 FMA.
// =====================================================================
#define BM 128
#define BN 128
#define BKK 8

__global__ __launch_bounds__(256) void k_xproj(const float* __restrict__ A,
                                               const float* __restrict__ B,
                                               const float* __restrict__ bias) {
    __shared__ float As[BKK][BM];
    __shared__ float Bs[BKK][BN];
    const int Kd = DDIM, Nd = GDIM;
    const int brow = blockIdx.y * BM;
    const int bcol = blockIdx.x * BN;
    const int tid = threadIdx.x;
    const int tx = tid & 15, ty = tid >> 4;

    ull acc[8][4];
#pragma unroll
    for (int i = 0; i < 8; i++)
#pragma unroll
        for (int p = 0; p < 4; p++) acc[i][p] = 0ull;

    const int a_row = tid >> 1, a_k = (tid & 1) << 2;
    const int b_k = tid >> 5,  b_n = (tid & 31) << 2;
    const float* Ap = A + (size_t)brow * Kd;
    const float* Bp = B + bcol;

    for (int k0 = 0; k0 < Kd; k0 += BKK) {
        float4 av = *(const float4*)(Ap + (size_t)a_row * Kd + k0 + a_k);
        As[a_k + 0][a_row] = av.x;
        As[a_k + 1][a_row] = av.y;
        As[a_k + 2][a_row] = av.z;
        As[a_k + 3][a_row] = av.w;
        float4 bv = *(const float4*)(Bp + (size_t)(k0 + b_k) * Nd + b_n);
        *(float4*)&Bs[b_k][b_n] = bv;
        __syncthreads();

#pragma unroll
        for (int kk = 0; kk < BKK; kk++) {
            float4 a0 = *(const float4*)&As[kk][ty * 8];
            float4 a1 = *(const float4*)&As[kk][ty * 8 + 4];
            float4 b0 = *(const float4*)&Bs[kk][tx * 8];
            float4 b1 = *(const float4*)&Bs[kk][tx * 8 + 4];
            float ar[8] = {a0.x, a0.y, a0.z, a0.w, a1.x, a1.y, a1.z, a1.w};
            ull bp0, bp1, bp2, bp3;
            PACK_XY(bp0, b0.x, b0.y);
            PACK_XY(bp1, b0.z, b0.w);
            PACK_XY(bp2, b1.x, b1.y);
            PACK_XY(bp3, b1.z, b1.w);
#pragma unroll
            for (int i = 0; i < 8; i++) {
                ull aa;
                PACK_DUP(aa, ar[i]);
                FMA_X2(acc[i][0], aa, bp0);
                FMA_X2(acc[i][1], aa, bp1);
                FMA_X2(acc[i][2], aa, bp2);
                FMA_X2(acc[i][3], aa, bp3);
            }
        }
        __syncthreads();
    }

#pragma unroll
    for (int i = 0; i < 8; i++) {
        size_t r = (size_t)(brow + ty * 8 + i);
        int cidx = bcol + tx * 8;
        float o[8];
#pragma unroll
        for (int p = 0; p < 4; p++) {
            float lo, hi;
            UNPACK(lo, hi, acc[i][p]);
            o[2 * p]     = lo + bias[cidx + 2 * p];
            o[2 * p + 1] = hi + bias[cidx + 2 * p + 1];
        }
        float4 v0 = {o[0], o[1], o[2], o[3]};
        float4 v1 = {o[4], o[5], o[6], o[7]};
        *(float4*)(g_xproj + r * Nd + cidx)     = v0;
        *(float4*)(g_xproj + r * Nd + cidx + 4) = v1;
    }
}

// =====================================================================
// Kernel 2: persistent masked-LSTM recurrence, f32x2 GEMM.
// 128 CTAs x 256 threads, each CTA owns 4 h-cols (16 gate cols).
// Thread tile: 4 rows x 8 cols x (k-slice of 64), 8-way shfl reduce.
// Lane layout: lane[0:3)=ks, lane[3:5)=rt_low; warp = ct + 2*rt_high.
// =====================================================================
#define NCTA 128
#define NTHR 256

// smem layout (floats):
//   h_s:     [64][512] swizzled            32768
//   w_s:     [512][32] swizzled (16 cols)  16384
//   keep_s:  [64]                          64
//   gates_s: [64][17]                      1088
#define OFF_H  0
#define OFF_W  32768
#define OFF_KEEP 49152
#define OFF_GATES 49216
#define SMEM2 ((49216 + 64 * 17) * 4)

__global__ __launch_bounds__(NTHR, 1) void k_rnn(const float* __restrict__ h0,
                                                 const float* __restrict__ c0,
                                                 const float* __restrict__ mask,
                                                 const float* __restrict__ Wh,
                                                 float* __restrict__ out) {
    extern __shared__ float sm[];
    float* h_s     = sm + OFF_H;
    float* w_s     = sm + OFF_W;
    float* keep_s  = sm + OFF_KEEP;
    float* gates_s = sm + OFF_GATES;

    const int tid = threadIdx.x;
    const int cta = blockIdx.x;
    const int hc0 = cta * 4;

    // GEMM thread coords
    const int ks  = tid & 7;            // k-slice: k in [ks*64, ks*64+64)
    const int rtl = (tid >> 3) & 3;
    const int wid = tid >> 5;
    const int ct  = wid & 1;            // col-tile: cols ct*8 .. ct*8+7
    const int rth = wid >> 1;
    const int rt  = rth * 4 + rtl;      // row-tile: rows rt*4 .. rt*4+3
    const int row0 = rt * 4;
    const int qh  = ((rt + ks) & 7) << 2;   // h swizzle offset for this thread
    const int kbase0 = ks * 64;
    // w pair slots (constant per thread): pair p covers cols ct*8+2p, +2p+1
    const int ws0 = (((ct * 8) + 0) ^ (ks << 2)) >> 1;
    const int ws1 = (((ct * 8) + 2) ^ (ks << 2)) >> 1;
    const int ws2 = (((ct * 8) + 4) ^ (ks << 2)) >> 1;
    const int ws3 = (((ct * 8) + 6) ^ (ks << 2)) >> 1;

    // Stage Wh slice (once): w_s[k][c] swizzled, c in 0..15
    for (int i = tid; i < 512 * 16; i += NTHR) {
        int k = i >> 4, c = i & 15;
        int gcol = (c >> 2) * HID + hc0 + (c & 3);
        int slot = c ^ (((k >> 6) & 7) << 2);
        w_s[k * 32 + slot] = Wh[(size_t)k * GDIM + gcol];
    }

    // Update-phase mapping
    const int ub = tid >> 2;
    const int uj = tid & 3;
    float c_reg = c0[ub * HID + hc0 + uj];
    float h_last = 0.0f;

    unsigned int bar_target = 0;
    if (tid == 0) bar_target = *((volatile unsigned int*)&g_bar_gen);

    __syncthreads();  // w_s ready

    for (int t = 0; t < T_STEPS; t++) {
        // xp prefetch (owners only: ks==0). 4 rows x 2 gates, float4 each.
        float4 xpv[4][2];
        if (ks == 0) {
            const float* xb = g_xproj + (size_t)t * BATCH * GDIM;
#pragma unroll
            for (int i = 0; i < 4; i++)
#pragma unroll
                for (int g = 0; g < 2; g++)
                    xpv[i][g] = *(const float4*)&xb[(size_t)(row0 + i) * GDIM +
                                                    (2 * ct + g) * HID + hc0];
        }

        if (tid < BATCH) keep_s[tid] = 1.0f - mask[t * BATCH + tid];
        __syncthreads();

        // Stage h (reset-masked) into swizzled smem
        const float4* hsrc = (const float4*)((t == 0) ? h0 : (const float*)g_h);
        for (int i = tid; i < (BATCH * HID) / 4; i += NTHR) {
            int row = i >> 7;
            int k   = (i & 127) << 2;
            float4 v = hsrc[i];
            float kp = keep_s[row];
            v.x *= kp; v.y *= kp; v.z *= kp; v.w *= kp;
            int q = (((row >> 2) + (k >> 6)) & 7) << 2;
            *(float4*)&h_s[row * 512 + (k ^ q)] = v;
        }
        __syncthreads();

        // ---- GEMM: acc[4 rows][4 col-pairs], k-slice of 64 ----
        ull acc[4][4];
#pragma unroll
        for (int i = 0; i < 4; i++)
#pragma unroll
            for (int p = 0; p < 4; p++) acc[i][p] = 0ull;

#pragma unroll 4
        for (int g = 0; g < 16; g++) {
            int kb = kbase0 + g * 4;
            int koff = kb ^ qh;
            float4 h0v = *(const float4*)&h_s[(row0 + 0) * 512 + koff];
            float4 h1v = *(const float4*)&h_s[(row0 + 1) * 512 + koff];
            float4 h2v = *(const float4*)&h_s[(row0 + 2) * 512 + koff];
            float4 h3v = *(const float4*)&h_s[(row0 + 3) * 512 + koff];
            float ha[4] = {h0v.x, h0v.y, h0v.z, h0v.w};
            float hb[4] = {h1v.x, h1v.y, h1v.z, h1v.w};
            float hc[4] = {h2v.x, h2v.y, h2v.z, h2v.w};
            float hd[4] = {h3v.x, h3v.y, h3v.z, h3v.w};
#pragma unroll
            for (int dk = 0; dk < 4; dk++) {
                const ull* wp = (const ull*)(w_s + (size_t)(kb + dk) * 32);
                ull w0 = wp[ws0], w1 = wp[ws1], w2 = wp[ws2], w3 = wp[ws3];
                ull aa;
                PACK_DUP(aa, ha[dk]);
                FMA_X2(acc[0][0], aa, w0); FMA_X2(acc[0][1], aa, w1);
                FMA_X2(acc[0][2], aa, w2); FMA_X2(acc[0][3], aa, w3);
                PACK_DUP(aa, hb[dk]);
                FMA_X2(acc[1][0], aa, w0); FMA_X2(acc[1][1], aa, w1);
                FMA_X2(acc[1][2], aa, w2); FMA_X2(acc[1][3], aa, w3);
                PACK_DUP(aa, hc[dk]);
                FMA_X2(acc[2][0], aa, w0); FMA_X2(acc[2][1], aa, w1);
                FMA_X2(acc[2][2], aa, w2); FMA_X2(acc[2][3], aa, w3);
                PACK_DUP(aa, hd[dk]);
                FMA_X2(acc[3][0], aa, w0); FMA_X2(acc[3][1], aa, w1);
                FMA_X2(acc[3][2], aa, w2); FMA_X2(acc[3][3], aa, w3);
            }
        }

        // ---- 8-way shfl reduce over ks (lane bits 0..2) ----
#pragma unroll
        for (int m = 1; m < 8; m <<= 1) {
#pragma unroll
            for (int i = 0; i < 4; i++)
#pragma unroll
                for (int p = 0; p < 4; p++) {
                    ull o = __shfl_xor_sync(0xffffffffu, acc[i][p], m);
                    ADD_X2(acc[i][p], acc[i][p], o);
                }
        }

        // Owners add xp and write gates
        if (ks == 0) {
#pragma unroll
            for (int i = 0; i < 4; i++) {
                float g0lo, g0hi, g1lo, g1hi, g2lo, g2hi, g3lo, g3hi;
                UNPACK(g0lo, g0hi, acc[i][0]);
                UNPACK(g1lo, g1hi, acc[i][1]);
                UNPACK(g2lo, g2hi, acc[i][2]);
                UNPACK(g3lo, g3hi, acc[i][3]);
                float* gr = &gates_s[(row0 + i) * 17 + ct * 8];
                gr[0] = g0lo + xpv[i][0].x;
                gr[1] = g0hi + xpv[i][0].y;
                gr[2] = g1lo + xpv[i][0].z;
                gr[3] = g1hi + xpv[i][0].w;
                gr[4] = g2lo + xpv[i][1].x;
                gr[5] = g2hi + xpv[i][1].y;
                gr[6] = g3lo + xpv[i][1].z;
                gr[7] = g3hi + xpv[i][1].w;
            }
        }
        __syncthreads();

        // ---- LSTM cell update ----
        {
            float kp = keep_s[ub];
            float ig = gates_s[ub * 17 + 0  + uj];
            float fg = gates_s[ub * 17 + 4  + uj];
            float gg = gates_s[ub * 17 + 8  + uj];
            float og = gates_s[ub * 17 + 12 + uj];
            float cprev = c_reg * kp;
            float cn = sigmoidf_(fg) * cprev + sigmoidf_(ig) * tanhf(gg);
            float hn = sigmoidf_(og) * tanhf(cn);
            c_reg = cn;
            h_last = hn;
            int hcol = hc0 + uj;
            out[(size_t)t * BATCH * HID + ub * HID + hcol] = hn;
            g_h[ub * HID + hcol] = hn;
        }
        __threadfence();

        // ---- software grid barrier ----
        __syncthreads();
        if (tid == 0) {
            bar_target += 1;
            unsigned int old = atomicAdd(&g_bar_count, 1);
            if (old == NCTA - 1) {
                atomicExch(&g_bar_count, 0);
                __threadfence();
                atomicAdd(&g_bar_gen, 1);
            } else {
                while ((int)(*((volatile unsigned int*)&g_bar_gen) - bar_target) < 0)
                    __nanosleep(32);
                __threadfence();
            }
        }
        __syncthreads();
    }

    // Finals
    float* hfin = out + (size_t)T_STEPS * BATCH * HID;
    float* cfin = hfin + BATCH * HID;
    hfin[ub * HID + hc0 + uj] = h_last;
    cfin[ub * HID + hc0 + uj] = c_reg;
}

// =====================================================================
extern "C" void kernel_launch(void* const* d_in, const int* in_sizes, int n_in,
                              void* d_out, int out_size) {
    (void)in_sizes; (void)n_in; (void)out_size;
    const float* x    = (const float*)d_in[0];
    const float* h0   = (const float*)d_in[1];
    const float* c0   = (const float*)d_in[2];
    const float* mask = (const float*)d_in[3];
    const float* Wx   = (const float*)d_in[4];
    const float* Wh   = (const float*)d_in[5];
    const float* b    = (const float*)d_in[6];
    float* out = (float*)d_out;

    dim3 g1(GDIM / BN, (T_STEPS * BATCH) / BM);
    k_xproj<<<g1, 256>>>(x, Wx, b);

    cudaFuncSetAttribute(k_rnn, cudaFuncAttributeMaxDynamicSharedMemorySize, SMEM2);
    k_rnn<<<NCTA, NTHR, SMEM2>>>(h0, c0, mask, Wh, out);
}

// round 3
// speedup vs baseline: 1.2257x; 1.0359x over previous
#include <cuda_runtime.h>
#include <math.h>

// Problem constants (fixed by setup_inputs)
#define T_STEPS 512
#define BATCH   64
#define HID     512
#define GDIM    2048   // 4*H
#define DDIM    512

typedef unsigned long long ull;

// ---- scratch (device globals: allocation-free rule) ----
__device__ float g_xproj[(size_t)T_STEPS * BATCH * GDIM];  // 268 MB
__device__ float g_h[BATCH * HID];
__device__ unsigned int g_bar_count = 0;
__device__ unsigned int g_bar_gen   = 0;

__device__ __forceinline__ float sigmoidf_(float x) { return 1.0f / (1.0f + expf(-x)); }

// Packed fp32x2 ops (Blackwell 2x FP32; only reachable via PTX)
#define FMA_X2(acc, a, b) asm("fma.rn.f32x2 %0,%1,%2,%0;" : "+l"(acc) : "l"(a), "l"(b))
#define ADD_X2(d, a, b)   asm("add.rn.f32x2 %0,%1,%2;"    : "=l"(d)  : "l"(a), "l"(b))
#define PACK_DUP(d, x)    asm("mov.b64 %0,{%1,%1};"        : "=l"(d)  : "f"(x))
#define PACK_XY(d, x, y)  asm("mov.b64 %0,{%1,%2};"        : "=l"(d)  : "f"(x), "f"(y))
#define UNPACK(lo, hi, v) asm("mov.b64 {%0,%1},%2;"        : "=f"(lo), "=f"(hi) : "l"(v))

// =====================================================================
// Kernel 1: x_proj[M=T*B, N=4H] = X[M, D] @ Wx[D, 4H] + b
// 128x128x8 tiled, 256 threads, 8x8 microtile, packed f32x2 FMA.
// =====================================================================
#define BM 128
#define BN 128
#define BKK 8

__global__ __launch_bounds__(256) void k_xproj(const float* __restrict__ A,
                                               const float* __restrict__ B,
                                               const float* __restrict__ bias) {
    __shared__ float As[BKK][BM];
    __shared__ float Bs[BKK][BN];
    const int Kd = DDIM, Nd = GDIM;
    const int brow = blockIdx.y * BM;
    const int bcol = blockIdx.x * BN;
    const int tid = threadIdx.x;
    const int tx = tid & 15, ty = tid >> 4;

    ull acc[8][4];
#pragma unroll
    for (int i = 0; i < 8; i++)
#pragma unroll
        for (int p = 0; p < 4; p++) acc[i][p] = 0ull;

    const int a_row = tid >> 1, a_k = (tid & 1) << 2;
    const int b_k = tid >> 5,  b_n = (tid & 31) << 2;
    const float* Ap = A + (size_t)brow * Kd;
    const float* Bp = B + bcol;

    for (int k0 = 0; k0 < Kd; k0 += BKK) {
        float4 av = *(const float4*)(Ap + (size_t)a_row * Kd + k0 + a_k);
        As[a_k + 0][a_row] = av.x;
        As[a_k + 1][a_row] = av.y;
        As[a_k + 2][a_row] = av.z;
        As[a_k + 3][a_row] = av.w;
        float4 bv = *(const float4*)(Bp + (size_t)(k0 + b_k) * Nd + b_n);
        *(float4*)&Bs[b_k][b_n] = bv;
        __syncthreads();

#pragma unroll
        for (int kk = 0; kk < BKK; kk++) {
            float4 a0 = *(const float4*)&As[kk][ty * 8];
            float4 a1 = *(const float4*)&As[kk][ty * 8 + 4];
            float4 b0 = *(const float4*)&Bs[kk][tx * 8];
            float4 b1 = *(const float4*)&Bs[kk][tx * 8 + 4];
            float ar[8] = {a0.x, a0.y, a0.z, a0.w, a1.x, a1.y, a1.z, a1.w};
            ull bp0, bp1, bp2, bp3;
            PACK_XY(bp0, b0.x, b0.y);
            PACK_XY(bp1, b0.z, b0.w);
            PACK_XY(bp2, b1.x, b1.y);
            PACK_XY(bp3, b1.z, b1.w);
#pragma unroll
            for (int i = 0; i < 8; i++) {
                ull aa;
                PACK_DUP(aa, ar[i]);
                FMA_X2(acc[i][0], aa, bp0);
                FMA_X2(acc[i][1], aa, bp1);
                FMA_X2(acc[i][2], aa, bp2);
                FMA_X2(acc[i][3], aa, bp3);
            }
        }
        __syncthreads();
    }

#pragma unroll
    for (int i = 0; i < 8; i++) {
        size_t r = (size_t)(brow + ty * 8 + i);
        int cidx = bcol + tx * 8;
        float o[8];
#pragma unroll
        for (int p = 0; p < 4; p++) {
            float lo, hi;
            UNPACK(lo, hi, acc[i][p]);
            o[2 * p]     = lo + bias[cidx + 2 * p];
            o[2 * p + 1] = hi + bias[cidx + 2 * p + 1];
        }
        float4 v0 = {o[0], o[1], o[2], o[3]};
        float4 v1 = {o[4], o[5], o[6], o[7]};
        *(float4*)(g_xproj + r * Nd + cidx)     = v0;
        *(float4*)(g_xproj + r * Nd + cidx + 4) = v1;
    }
}

// =====================================================================
// Kernel 2: persistent masked-LSTM recurrence, f32x2 GEMM, 512 threads.
// 128 CTAs x 512 threads (16 warps/SM for latency hiding).
// Thread tile: 2 rows x 8 cols x (k-slice of 64), 8-way shfl reduce.
// Lane layout: lane[0:3)=ks, lane[3:5)=rtl; warp: bit0=ct, bits1-3=rth.
// =====================================================================
#define NCTA 128
#define NTHR 512

// smem layout (floats):
//   h_s:     [64][512] swizzled            32768
//   w_s:     [512][32] swizzled (16 cols)  16384
//   gates_s: [64][17]                      1088
#define OFF_H  0
#define OFF_W  32768
#define OFF_GATES 49152
#define SMEM2 ((49152 + 64 * 17) * 4)

__global__ __launch_bounds__(NTHR, 1) void k_rnn(const float* __restrict__ h0,
                                                 const float* __restrict__ c0,
                                                 const float* __restrict__ mask,
                                                 const float* __restrict__ Wh,
                                                 float* __restrict__ out) {
    extern __shared__ float sm[];
    float* h_s     = sm + OFF_H;
    float* w_s     = sm + OFF_W;
    float* gates_s = sm + OFF_GATES;

    const int tid = threadIdx.x;
    const int cta = blockIdx.x;
    const int hc0 = cta * 4;

    // GEMM thread coords
    const int lane = tid & 31;
    const int wid  = tid >> 5;          // 0..15
    const int ks   = lane & 7;          // k-slice: [ks*64, ks*64+64)
    const int rtl  = (lane >> 3) & 3;
    const int ct   = wid & 1;           // col-tile: cols ct*8 .. ct*8+7
    const int rth  = wid >> 1;          // 0..7
    const int rt   = rth * 4 + rtl;     // 0..31
    const int row0 = rt * 2;            // 2 rows per thread
    const int qh   = (((rt >> 1) + ks) & 7) << 2;
    const int kbase0 = ks * 64;
    const int ws0 = (((ct * 8) + 0) ^ (ks << 2)) >> 1;
    const int ws1 = (((ct * 8) + 2) ^ (ks << 2)) >> 1;
    const int ws2 = (((ct * 8) + 4) ^ (ks << 2)) >> 1;
    const int ws3 = (((ct * 8) + 6) ^ (ks << 2)) >> 1;

    // Stage Wh slice (once): w_s[k][c] swizzled, c in 0..15
    for (int i = tid; i < 512 * 16; i += NTHR) {
        int k = i >> 4, c = i & 15;
        int gcol = (c >> 2) * HID + hc0 + (c & 3);
        int slot = c ^ (((k >> 6) & 7) << 2);
        w_s[k * 32 + slot] = Wh[(size_t)k * GDIM + gcol];
    }

    // Update-phase mapping (first 256 threads)
    const int ub = tid >> 2;
    const int uj = tid & 3;
    float c_reg = 0.0f, h_last = 0.0f;
    if (tid < 256) c_reg = c0[ub * HID + hc0 + uj];

    unsigned int bar_target = 0;
    if (tid == 0) bar_target = *((volatile unsigned int*)&g_bar_gen);

    __syncthreads();  // w_s ready

    for (int t = 0; t < T_STEPS; t++) {
        // xp prefetch (owners only: ks==0). 2 rows x 2 gates, float4 each.
        float4 xpv[2][2];
        if (ks == 0) {
            const float* xb = g_xproj + (size_t)t * BATCH * GDIM;
#pragma unroll
            for (int i = 0; i < 2; i++)
#pragma unroll
                for (int g = 0; g < 2; g++)
                    xpv[i][g] = *(const float4*)&xb[(size_t)(row0 + i) * GDIM +
                                                    (2 * ct + g) * HID + hc0];
        }

        // Stage h (reset-masked) into swizzled smem; keep read from mask (L1)
        const float4* hsrc = (const float4*)((t == 0) ? h0 : (const float*)g_h);
        const float* mrow = mask + t * BATCH;
#pragma unroll
        for (int ii = 0; ii < (BATCH * HID) / 4 / NTHR; ii++) {
            int i = tid + ii * NTHR;
            int row = i >> 7;
            int k   = (i & 127) << 2;
            float4 v = hsrc[i];
            float kp = 1.0f - __ldg(&mrow[row]);
            v.x *= kp; v.y *= kp; v.z *= kp; v.w *= kp;
            int q = (((row >> 2) + (k >> 6)) & 7) << 2;
            *(float4*)&h_s[row * 512 + (k ^ q)] = v;
        }
        __syncthreads();

        // ---- GEMM: acc[2 rows][4 col-pairs], k-slice of 64 ----
        ull acc[2][4];
#pragma unroll
        for (int i = 0; i < 2; i++)
#pragma unroll
            for (int p = 0; p < 4; p++) acc[i][p] = 0ull;

#pragma unroll 4
        for (int g = 0; g < 16; g++) {
            int kb = kbase0 + g * 4;
            int koff = kb ^ qh;
            float4 h0v = *(const float4*)&h_s[(row0 + 0) * 512 + koff];
            float4 h1v = *(const float4*)&h_s[(row0 + 1) * 512 + koff];
            float ha[4] = {h0v.x, h0v.y, h0v.z, h0v.w};
            float hb[4] = {h1v.x, h1v.y, h1v.z, h1v.w};
#pragma unroll
            for (int dk = 0; dk < 4; dk++) {
                const ull* wp = (const ull*)(w_s + (size_t)(kb + dk) * 32);
                ull w0 = wp[ws0], w1 = wp[ws1], w2 = wp[ws2], w3 = wp[ws3];
                ull aa;
                PACK_DUP(aa, ha[dk]);
                FMA_X2(acc[0][0], aa, w0); FMA_X2(acc[0][1], aa, w1);
                FMA_X2(acc[0][2], aa, w2); FMA_X2(acc[0][3], aa, w3);
                PACK_DUP(aa, hb[dk]);
                FMA_X2(acc[1][0], aa, w0); FMA_X2(acc[1][1], aa, w1);
                FMA_X2(acc[1][2], aa, w2); FMA_X2(acc[1][3], aa, w3);
            }
        }

        // ---- 8-way shfl reduce over ks (lane bits 0..2) ----
#pragma unroll
        for (int m = 1; m < 8; m <<= 1) {
#pragma unroll
            for (int i = 0; i < 2; i++)
#pragma unroll
                for (int p = 0; p < 4; p++) {
                    ull o = __shfl_xor_sync(0xffffffffu, acc[i][p], m);
                    ADD_X2(acc[i][p], acc[i][p], o);
                }
        }

        // Owners add xp and write gates
        if (ks == 0) {
#pragma unroll
            for (int i = 0; i < 2; i++) {
                float g0lo, g0hi, g1lo, g1hi, g2lo, g2hi, g3lo, g3hi;
                UNPACK(g0lo, g0hi, acc[i][0]);
                UNPACK(g1lo, g1hi, acc[i][1]);
                UNPACK(g2lo, g2hi, acc[i][2]);
                UNPACK(g3lo, g3hi, acc[i][3]);
                float* gr = &gates_s[(row0 + i) * 17 + ct * 8];
                gr[0] = g0lo + xpv[i][0].x;
                gr[1] = g0hi + xpv[i][0].y;
                gr[2] = g1lo + xpv[i][0].z;
                gr[3] = g1hi + xpv[i][0].w;
                gr[4] = g2lo + xpv[i][1].x;
                gr[5] = g2hi + xpv[i][1].y;
                gr[6] = g3lo + xpv[i][1].z;
                gr[7] = g3hi + xpv[i][1].w;
            }
        }
        __syncthreads();

        // ---- LSTM cell update (threads 0..255) ----
        if (tid < 256) {
            float kp = 1.0f - __ldg(&mrow[ub]);
            float ig = gates_s[ub * 17 + 0  + uj];
            float fg = gates_s[ub * 17 + 4  + uj];
            float gg = gates_s[ub * 17 + 8  + uj];
            float og = gates_s[ub * 17 + 12 + uj];
            float cprev = c_reg * kp;
            float cn = sigmoidf_(fg) * cprev + sigmoidf_(ig) * tanhf(gg);
            float hn = sigmoidf_(og) * tanhf(cn);
            c_reg = cn;
            h_last = hn;
            int hcol = hc0 + uj;
            out[(size_t)t * BATCH * HID + ub * HID + hcol] = hn;
            g_h[ub * HID + hcol] = hn;
        }

        // ---- software grid barrier (single GPU-scope fence from tid0) ----
        __syncthreads();
        if (tid == 0) {
            asm volatile("fence.acq_rel.gpu;" ::: "memory");
            bar_target += 1;
            unsigned int old = atomicAdd(&g_bar_count, 1);
            if (old == NCTA - 1) {
                atomicExch(&g_bar_count, 0);
                atomicAdd(&g_bar_gen, 1);
            } else {
                while ((int)(*((volatile unsigned int*)&g_bar_gen) - bar_target) < 0)
                    __nanosleep(32);
            }
            asm volatile("fence.acq_rel.gpu;" ::: "memory");
        }
        __syncthreads();
    }

    // Finals
    if (tid < 256) {
        float* hfin = out + (size_t)T_STEPS * BATCH * HID;
        float* cfin = hfin + BATCH * HID;
        hfin[ub * HID + hc0 + uj] = h_last;
        cfin[ub * HID + hc0 + uj] = c_reg;
    }
}

// =====================================================================
extern "C" void kernel_launch(void* const* d_in, const int* in_sizes, int n_in,
                              void* d_out, int out_size) {
    (void)in_sizes; (void)n_in; (void)out_size;
    const float* x    = (const float*)d_in[0];
    const float* h0   = (const float*)d_in[1];
    const float* c0   = (const float*)d_in[2];
    const float* mask = (const float*)d_in[3];
    const float* Wx   = (const float*)d_in[4];
    const float* Wh   = (const float*)d_in[5];
    const float* b    = (const float*)d_in[6];
    float* out = (float*)d_out;

    dim3 g1(GDIM / BN, (T_STEPS * BATCH) / BM);
    k_xproj<<<g1, 256>>>(x, Wx, b);

    cudaFuncSetAttribute(k_rnn, cudaFuncAttributeMaxDynamicSharedMemorySize, SMEM2);
    k_rnn<<<NCTA, NTHR, SMEM2>>>(h0, c0, mask, Wh, out);
}

// round 4
// speedup vs baseline: 1.2275x; 1.0014x over previous
#include <cuda_runtime.h>
#include <math.h>

// Problem constants (fixed by setup_inputs)
#define T_STEPS 512
#define BATCH   64
#define HID     512
#define GDIM    2048   // 4*H
#define DDIM    512

typedef unsigned long long ull;

// ---- scratch (device globals: allocation-free rule) ----
__device__ float g_xproj[(size_t)T_STEPS * BATCH * GDIM];  // 268 MB
__device__ float g_h[BATCH * HID];
__device__ unsigned int g_bar_count = 0;
__device__ unsigned int g_bar_gen   = 0;

__device__ __forceinline__ float sigmoidf_(float x) { return 1.0f / (1.0f + expf(-x)); }

// Packed fp32x2 ops (Blackwell 2x FP32; only reachable via PTX)
#define FMA_X2(acc, a, b) asm("fma.rn.f32x2 %0,%1,%2,%0;" : "+l"(acc) : "l"(a), "l"(b))
#define ADD_X2(d, a, b)   asm("add.rn.f32x2 %0,%1,%2;"    : "=l"(d)  : "l"(a), "l"(b))
#define PACK_DUP(d, x)    asm("mov.b64 %0,{%1,%1};"        : "=l"(d)  : "f"(x))
#define PACK_XY(d, x, y)  asm("mov.b64 %0,{%1,%2};"        : "=l"(d)  : "f"(x), "f"(y))
#define UNPACK(lo, hi, v) asm("mov.b64 {%0,%1},%2;"        : "=f"(lo), "=f"(hi) : "l"(v))

// =====================================================================
// Kernel 1: x_proj[M=T*B, N=4H] = X[M, D] @ Wx[D, 4H] + b
// 128x128x8 tiled, 256 threads, 8x8 microtile, packed f32x2 FMA.
// =====================================================================
#define BM 128
#define BN 128
#define BKK 8

__global__ __launch_bounds__(256) void k_xproj(const float* __restrict__ A,
                                               const float* __restrict__ B,
                                               const float* __restrict__ bias) {
    __shared__ float As[BKK][BM];
    __shared__ float Bs[BKK][BN];
    const int Kd = DDIM, Nd = GDIM;
    const int brow = blockIdx.y * BM;
    const int bcol = blockIdx.x * BN;
    const int tid = threadIdx.x;
    const int tx = tid & 15, ty = tid >> 4;

    ull acc[8][4];
#pragma unroll
    for (int i = 0; i < 8; i++)
#pragma unroll
        for (int p = 0; p < 4; p++) acc[i][p] = 0ull;

    const int a_row = tid >> 1, a_k = (tid & 1) << 2;
    const int b_k = tid >> 5,  b_n = (tid & 31) << 2;
    const float* Ap = A + (size_t)brow * Kd;
    const float* Bp = B + bcol;

    for (int k0 = 0; k0 < Kd; k0 += BKK) {
        float4 av = *(const float4*)(Ap + (size_t)a_row * Kd + k0 + a_k);
        As[a_k + 0][a_row] = av.x;
        As[a_k + 1][a_row] = av.y;
        As[a_k + 2][a_row] = av.z;
        As[a_k + 3][a_row] = av.w;
        float4 bv = *(const float4*)(Bp + (size_t)(k0 + b_k) * Nd + b_n);
        *(float4*)&Bs[b_k][b_n] = bv;
        __syncthreads();

#pragma unroll
        for (int kk = 0; kk < BKK; kk++) {
            float4 a0 = *(const float4*)&As[kk][ty * 8];
            float4 a1 = *(const float4*)&As[kk][ty * 8 + 4];
            float4 b0 = *(const float4*)&Bs[kk][tx * 8];
            float4 b1 = *(const float4*)&Bs[kk][tx * 8 + 4];
            float ar[8] = {a0.x, a0.y, a0.z, a0.w, a1.x, a1.y, a1.z, a1.w};
            ull bp0, bp1, bp2, bp3;
            PACK_XY(bp0, b0.x, b0.y);
            PACK_XY(bp1, b0.z, b0.w);
            PACK_XY(bp2, b1.x, b1.y);
            PACK_XY(bp3, b1.z, b1.w);
#pragma unroll
            for (int i = 0; i < 8; i++) {
                ull aa;
                PACK_DUP(aa, ar[i]);
                FMA_X2(acc[i][0], aa, bp0);
                FMA_X2(acc[i][1], aa, bp1);
                FMA_X2(acc[i][2], aa, bp2);
                FMA_X2(acc[i][3], aa, bp3);
            }
        }
        __syncthreads();
    }

#pragma unroll
    for (int i = 0; i < 8; i++) {
        size_t r = (size_t)(brow + ty * 8 + i);
        int cidx = bcol + tx * 8;
        float o[8];
#pragma unroll
        for (int p = 0; p < 4; p++) {
            float lo, hi;
            UNPACK(lo, hi, acc[i][p]);
            o[2 * p]     = lo + bias[cidx + 2 * p];
            o[2 * p + 1] = hi + bias[cidx + 2 * p + 1];
        }
        float4 v0 = {o[0], o[1], o[2], o[3]};
        float4 v1 = {o[4], o[5], o[6], o[7]};
        *(float4*)(g_xproj + r * Nd + cidx)     = v0;
        *(float4*)(g_xproj + r * Nd + cidx + 4) = v1;
    }
}

// =====================================================================
// Kernel 2: persistent masked-LSTM recurrence, f32x2 GEMM, 512 threads.
// 128 CTAs x 512 threads (16 warps/SM for latency hiding).
// Thread tile: 2 rows x 8 cols x (k-slice of 64), 8-way shfl reduce.
// Lane layout: lane[0:3)=ks, lane[3:5)=rtl; warp: bit0=ct, bits1-3=rth.
// =====================================================================
#define NCTA 128
#define NTHR 512

// smem layout (floats):
//   h_s:     [64][512] swizzled            32768
//   w_s:     [512][32] swizzled (16 cols)  16384
//   gates_s: [64][17]                      1088
#define OFF_H  0
#define OFF_W  32768
#define OFF_GATES 49152
#define SMEM2 ((49152 + 64 * 17) * 4)

__global__ __launch_bounds__(NTHR, 1) void k_rnn(const float* __restrict__ h0,
                                                 const float* __restrict__ c0,
                                                 const float* __restrict__ mask,
                                                 const float* __restrict__ Wh,
                                                 float* __restrict__ out) {
    extern __shared__ float sm[];
    float* h_s     = sm + OFF_H;
    float* w_s     = sm + OFF_W;
    float* gates_s = sm + OFF_GATES;

    const int tid = threadIdx.x;
    const int cta = blockIdx.x;
    const int hc0 = cta * 4;

    // GEMM thread coords
    const int lane = tid & 31;
    const int wid  = tid >> 5;          // 0..15
    const int ks   = lane & 7;          // k-slice: [ks*64, ks*64+64)
    const int rtl  = (lane >> 3) & 3;
    const int ct   = wid & 1;           // col-tile: cols ct*8 .. ct*8+7
    const int rth  = wid >> 1;          // 0..7
    const int rt   = rth * 4 + rtl;     // 0..31
    const int row0 = rt * 2;            // 2 rows per thread
    const int qh   = (((rt >> 1) + ks) & 7) << 2;
    const int kbase0 = ks * 64;
    const int ws0 = (((ct * 8) + 0) ^ (ks << 2)) >> 1;
    const int ws1 = (((ct * 8) + 2) ^ (ks << 2)) >> 1;
    const int ws2 = (((ct * 8) + 4) ^ (ks << 2)) >> 1;
    const int ws3 = (((ct * 8) + 6) ^ (ks << 2)) >> 1;

    // Stage Wh slice (once): w_s[k][c] swizzled, c in 0..15
    for (int i = tid; i < 512 * 16; i += NTHR) {
        int k = i >> 4, c = i & 15;
        int gcol = (c >> 2) * HID + hc0 + (c & 3);
        int slot = c ^ (((k >> 6) & 7) << 2);
        w_s[k * 32 + slot] = Wh[(size_t)k * GDIM + gcol];
    }

    // Update-phase mapping (first 256 threads)
    const int ub = tid >> 2;
    const int uj = tid & 3;
    float c_reg = 0.0f, h_last = 0.0f;
    if (tid < 256) c_reg = c0[ub * HID + hc0 + uj];

    unsigned int bar_target = 0;
    if (tid == 0) bar_target = *((volatile unsigned int*)&g_bar_gen);

    __syncthreads();  // w_s ready

    for (int t = 0; t < T_STEPS; t++) {
        // xp prefetch (owners only: ks==0). 2 rows x 2 gates, float4 each.
        float4 xpv[2][2];
        if (ks == 0) {
            const float* xb = g_xproj + (size_t)t * BATCH * GDIM;
#pragma unroll
            for (int i = 0; i < 2; i++)
#pragma unroll
                for (int g = 0; g < 2; g++)
                    xpv[i][g] = *(const float4*)&xb[(size_t)(row0 + i) * GDIM +
                                                    (2 * ct + g) * HID + hc0];
        }

        // Stage h (reset-masked) into swizzled smem; keep read from mask (L1)
        const float4* hsrc = (const float4*)((t == 0) ? h0 : (const float*)g_h);
        const float* mrow = mask + t * BATCH;
#pragma unroll
        for (int ii = 0; ii < (BATCH * HID) / 4 / NTHR; ii++) {
            int i = tid + ii * NTHR;
            int row = i >> 7;
            int k   = (i & 127) << 2;
            float4 v = hsrc[i];
            float kp = 1.0f - __ldg(&mrow[row]);
            v.x *= kp; v.y *= kp; v.z *= kp; v.w *= kp;
            int q = (((row >> 2) + (k >> 6)) & 7) << 2;
            *(float4*)&h_s[row * 512 + (k ^ q)] = v;
        }
        __syncthreads();

        // ---- GEMM: acc[2 rows][4 col-pairs], k-slice of 64 ----
        ull acc[2][4];
#pragma unroll
        for (int i = 0; i < 2; i++)
#pragma unroll
            for (int p = 0; p < 4; p++) acc[i][p] = 0ull;

#pragma unroll 4
        for (int g = 0; g < 16; g++) {
            int kb = kbase0 + g * 4;
            int koff = kb ^ qh;
            float4 h0v = *(const float4*)&h_s[(row0 + 0) * 512 + koff];
            float4 h1v = *(const float4*)&h_s[(row0 + 1) * 512 + koff];
            float ha[4] = {h0v.x, h0v.y, h0v.z, h0v.w};
            float hb[4] = {h1v.x, h1v.y, h1v.z, h1v.w};
#pragma unroll
            for (int dk = 0; dk < 4; dk++) {
                const ull* wp = (const ull*)(w_s + (size_t)(kb + dk) * 32);
                ull w0 = wp[ws0], w1 = wp[ws1], w2 = wp[ws2], w3 = wp[ws3];
                ull aa;
                PACK_DUP(aa, ha[dk]);
                FMA_X2(acc[0][0], aa, w0); FMA_X2(acc[0][1], aa, w1);
                FMA_X2(acc[0][2], aa, w2); FMA_X2(acc[0][3], aa, w3);
                PACK_DUP(aa, hb[dk]);
                FMA_X2(acc[1][0], aa, w0); FMA_X2(acc[1][1], aa, w1);
                FMA_X2(acc[1][2], aa, w2); FMA_X2(acc[1][3], aa, w3);
            }
        }

        // ---- 8-way shfl reduce over ks (lane bits 0..2) ----
#pragma unroll
        for (int m = 1; m < 8; m <<= 1) {
#pragma unroll
            for (int i = 0; i < 2; i++)
#pragma unroll
                for (int p = 0; p < 4; p++) {
                    ull o = __shfl_xor_sync(0xffffffffu, acc[i][p], m);
                    ADD_X2(acc[i][p], acc[i][p], o);
                }
        }

        // Owners add xp and write gates
        if (ks == 0) {
#pragma unroll
            for (int i = 0; i < 2; i++) {
                float g0lo, g0hi, g1lo, g1hi, g2lo, g2hi, g3lo, g3hi;
                UNPACK(g0lo, g0hi, acc[i][0]);
                UNPACK(g1lo, g1hi, acc[i][1]);
                UNPACK(g2lo, g2hi, acc[i][2]);
                UNPACK(g3lo, g3hi, acc[i][3]);
                float* gr = &gates_s[(row0 + i) * 17 + ct * 8];
                gr[0] = g0lo + xpv[i][0].x;
                gr[1] = g0hi + xpv[i][0].y;
                gr[2] = g1lo + xpv[i][0].z;
                gr[3] = g1hi + xpv[i][0].w;
                gr[4] = g2lo + xpv[i][1].x;
                gr[5] = g2hi + xpv[i][1].y;
                gr[6] = g3lo + xpv[i][1].z;
                gr[7] = g3hi + xpv[i][1].w;
            }
        }
        __syncthreads();

        // ---- LSTM cell update (threads 0..255) ----
        if (tid < 256) {
            float kp = 1.0f - __ldg(&mrow[ub]);
            float ig = gates_s[ub * 17 + 0  + uj];
            float fg = gates_s[ub * 17 + 4  + uj];
            float gg = gates_s[ub * 17 + 8  + uj];
            float og = gates_s[ub * 17 + 12 + uj];
            float cprev = c_reg * kp;
            float cn = sigmoidf_(fg) * cprev + sigmoidf_(ig) * tanhf(gg);
            float hn = sigmoidf_(og) * tanhf(cn);
            c_reg = cn;
            h_last = hn;
            int hcol = hc0 + uj;
            out[(size_t)t * BATCH * HID + ub * HID + hcol] = hn;
            g_h[ub * HID + hcol] = hn;
        }

        // ---- software grid barrier (single GPU-scope fence from tid0) ----
        __syncthreads();
        if (tid == 0) {
            asm volatile("fence.acq_rel.gpu;" ::: "memory");
            bar_target += 1;
            unsigned int old = atomicAdd(&g_bar_count, 1);
            if (old == NCTA - 1) {
                atomicExch(&g_bar_count, 0);
                atomicAdd(&g_bar_gen, 1);
            } else {
                while ((int)(*((volatile unsigned int*)&g_bar_gen) - bar_target) < 0)
                    __nanosleep(32);
            }
            asm volatile("fence.acq_rel.gpu;" ::: "memory");
        }
        __syncthreads();
    }

    // Finals
    if (tid < 256) {
        float* hfin = out + (size_t)T_STEPS * BATCH * HID;
        float* cfin = hfin + BATCH * HID;
        hfin[ub * HID + hc0 + uj] = h_last;
        cfin[ub * HID + hc0 + uj] = c_reg;
    }
}

// =====================================================================
extern "C" void kernel_launch(void* const* d_in, const int* in_sizes, int n_in,
                              void* d_out, int out_size) {
    (void)in_sizes; (void)n_in; (void)out_size;
    const float* x    = (const float*)d_in[0];
    const float* h0   = (const float*)d_in[1];
    const float* c0   = (const float*)d_in[2];
    const float* mask = (const float*)d_in[3];
    const float* Wx   = (const float*)d_in[4];
    const float* Wh   = (const float*)d_in[5];
    const float* b    = (const float*)d_in[6];
    float* out = (float*)d_out;

    dim3 g1(GDIM / BN, (T_STEPS * BATCH) / BM);
    k_xproj<<<g1, 256>>>(x, Wx, b);

    cudaFuncSetAttribute(k_rnn, cudaFuncAttributeMaxDynamicSharedMemorySize, SMEM2);
    k_rnn<<<NCTA, NTHR, SMEM2>>>(h0, c0, mask, Wh, out);
}

// round 6
// speedup vs baseline: 1.5785x; 1.2859x over previous
#include <cuda_runtime.h>
#include <cuda_bf16.h>
#include <math.h>
#include <stdint.h>

// Problem constants (fixed by setup_inputs)
#define T_STEPS 512
#define BATCH   64
#define HID     512
#define GDIM    2048   // 4*H
#define DDIM    512

typedef unsigned long long ull;

// ---- scratch (device globals: allocation-free rule) ----
__device__ float g_xproj[(size_t)T_STEPS * BATCH * GDIM];  // 268 MB
__device__ __align__(16) __nv_bfloat16 g_hhi[BATCH * HID];
__device__ __align__(16) __nv_bfloat16 g_hlo[BATCH * HID];
__device__ unsigned int g_bar_count = 0;
__device__ unsigned int g_bar_gen   = 0;

__device__ __forceinline__ float sigmoidf_(float x) { return 1.0f / (1.0f + expf(-x)); }

// Packed fp32x2 ops (k_xproj)
#define FMA_X2(acc, a, b) asm("fma.rn.f32x2 %0,%1,%2,%0;" : "+l"(acc) : "l"(a), "l"(b))
#define PACK_DUP(d, x)    asm("mov.b64 %0,{%1,%1};"        : "=l"(d)  : "f"(x))
#define PACK_XY(d, x, y)  asm("mov.b64 %0,{%1,%2};"        : "=l"(d)  : "f"(x), "f"(y))
#define UNPACK(lo, hi, v) asm("mov.b64 {%0,%1},%2;"        : "=f"(lo), "=f"(hi) : "l"(v))

__device__ __forceinline__ uint32_t smem_u32(const void* p) {
    uint32_t a;
    asm("{ .reg .u64 t; cvta.to.shared.u64 t, %1; cvt.u32.u64 %0, t; }" : "=r"(a) : "l"(p));
    return a;
}

// =====================================================================
// Kernel 1: x_proj = X @ Wx + b  (unchanged from round 4)
// =====================================================================
#define BM 128
#define BN 128
#define BKK 8

__global__ __launch_bounds__(256) void k_xproj(const float* __restrict__ A,
                                               const float* __restrict__ B,
                                               const float* __restrict__ bias) {
    __shared__ float As[BKK][BM];
    __shared__ float Bs[BKK][BN];
    const int Kd = DDIM, Nd = GDIM;
    const int brow = blockIdx.y * BM;
    const int bcol = blockIdx.x * BN;
    const int tid = threadIdx.x;
    const int tx = tid & 15, ty = tid >> 4;

    ull acc[8][4];
#pragma unroll
    for (int i = 0; i < 8; i++)
#pragma unroll
        for (int p = 0; p < 4; p++) acc[i][p] = 0ull;

    const int a_row = tid >> 1, a_k = (tid & 1) << 2;
    const int b_k = tid >> 5,  b_n = (tid & 31) << 2;
    const float* Ap = A + (size_t)brow * Kd;
    const float* Bp = B + bcol;

    for (int k0 = 0; k0 < Kd; k0 += BKK) {
        float4 av = *(const float4*)(Ap + (size_t)a_row * Kd + k0 + a_k);
        As[a_k + 0][a_row] = av.x;
        As[a_k + 1][a_row] = av.y;
        As[a_k + 2][a_row] = av.z;
        As[a_k + 3][a_row] = av.w;
        float4 bv = *(const float4*)(Bp + (size_t)(k0 + b_k) * Nd + b_n);
        *(float4*)&Bs[b_k][b_n] = bv;
        __syncthreads();

#pragma unroll
        for (int kk = 0; kk < BKK; kk++) {
            float4 a0 = *(const float4*)&As[kk][ty * 8];
            float4 a1 = *(const float4*)&As[kk][ty * 8 + 4];
            float4 b0 = *(const float4*)&Bs[kk][tx * 8];
            float4 b1 = *(const float4*)&Bs[kk][tx * 8 + 4];
            float ar[8] = {a0.x, a0.y, a0.z, a0.w, a1.x, a1.y, a1.z, a1.w};
            ull bp0, bp1, bp2, bp3;
            PACK_XY(bp0, b0.x, b0.y);
            PACK_XY(bp1, b0.z, b0.w);
            PACK_XY(bp2, b1.x, b1.y);
            PACK_XY(bp3, b1.z, b1.w);
#pragma unroll
            for (int i = 0; i < 8; i++) {
                ull aa;
                PACK_DUP(aa, ar[i]);
                FMA_X2(acc[i][0], aa, bp0);
                FMA_X2(acc[i][1], aa, bp1);
                FMA_X2(acc[i][2], aa, bp2);
                FMA_X2(acc[i][3], aa, bp3);
            }
        }
        __syncthreads();
    }

#pragma unroll
    for (int i = 0; i < 8; i++) {
        size_t r = (size_t)(brow + ty * 8 + i);
        int cidx = bcol + tx * 8;
        float o[8];
#pragma unroll
        for (int p = 0; p < 4; p++) {
            float lo, hi;
            UNPACK(lo, hi, acc[i][p]);
            o[2 * p]     = lo + bias[cidx + 2 * p];
            o[2 * p + 1] = hi + bias[cidx + 2 * p + 1];
        }
        float4 v0 = {o[0], o[1], o[2], o[3]};
        float4 v1 = {o[4], o[5], o[6], o[7]};
        *(float4*)(g_xproj + r * Nd + cidx)     = v0;
        *(float4*)(g_xproj + r * Nd + cidx + 4) = v1;
    }
}

// =====================================================================
// Kernel 2: persistent masked-LSTM recurrence on mma.sync (HMMA, bf16).
// 128 CTAs x 512 thr. Per CTA per step, gates[64x16] computed as a
// K=1536 virtual GEMM (split-bf16, 3 exact terms):
//   kc in [0,32):  h_hi x W_hi      kc in [32,64): h_lo x W_hi
//   kc in [64,96): h_hi x W_lo      (lo x lo term ~2^-18, dropped)
// A smem: h rows [64][1024] bf16 (hi | lo), row stride 2048B, swizzled.
// B smem: W rows [16][1024] bf16 (hi | lo), same layout.
// 8 MMA warps, one m16n8 output tile each, 96 k-chunks.
// =====================================================================
#define NCTA 128
#define NTHR 512

// smem byte offsets
#define OFF_A  0        // 64 rows x 2048B = 131072
#define OFF_B  131072   // 16 rows x 2048B = 32768
#define OFF_G  163840   // gates 64 x 17 floats = 4352
#define SMEM2  168448

// swizzled byte offset within a 2048B row: 16B unit XOR (row & 7)
__device__ __forceinline__ uint32_t swz(int row, int kbyte) {
    return (uint32_t)(row * 2048) + ((((uint32_t)kbyte >> 4) ^ (uint32_t)(row & 7)) << 4)
         + ((uint32_t)kbyte & 15u);
}

__global__ __launch_bounds__(NTHR, 1) void k_rnn(const float* __restrict__ h0,
                                                 const float* __restrict__ c0,
                                                 const float* __restrict__ mask,
                                                 const float* __restrict__ Wh,
                                                 float* __restrict__ out) {
    extern __shared__ char smraw[];
    const uint32_t smb = smem_u32(smraw);
    float* gates_s = (float*)(smraw + OFF_G);
    const int tid = threadIdx.x, lane = tid & 31, wid = tid >> 5;
    const int cta = blockIdx.x, hc0 = cta * 4;

    // ---- Wh slice -> B smem, split-bf16 (hi at k<512, lo at k>=512) ----
#pragma unroll 4
    for (int it = 0; it < 32; it++) {
        int e = tid + it * NTHR;           // 0..16383
        int n = e >> 10, k = e & 1023;     // n: 16 gate cols, k: 0..1023
        int gcol = (n >> 2) * HID + hc0 + (n & 3);
        float v = Wh[(size_t)(k & 511) * GDIM + gcol];
        __nv_bfloat16 hi = __float2bfloat16_rn(v);
        __nv_bfloat16 bv = (k < 512) ? hi : __float2bfloat16_rn(v - __bfloat162float(hi));
        *(__nv_bfloat16*)(smraw + OFF_B + swz(n, k * 2)) = bv;
    }

    // MMA warp coords (wid < 8): tile (mt, nt); mt: 16 rows, nt: 8 cols
    const int mt = wid & 3, nt = wid >> 2;
    const int ar = mt * 16 + (lane & 15);
    const uint32_t aRowBase = smb + OFF_A + (uint32_t)ar * 2048;
    const uint32_t sA = (uint32_t)(ar & 7) << 4;
    const uint32_t aHi = (uint32_t)((lane >> 4) & 1) << 4;   // +16B for col 8-15 mats
    const int br = nt * 8 + (lane & 7);
    const uint32_t bRowBase = smb + OFF_B + (uint32_t)br * 2048;
    const uint32_t sB = (uint32_t)(br & 7) << 4;
    const uint32_t bHi = (uint32_t)((lane >> 3) & 1) << 4;

    // Update-phase mapping (first 256 threads): element (ub, hc0+uj)
    const int ub = tid >> 2;
    const int uj = tid & 3;
    float c_reg = 0.0f, h_last = 0.0f;
    if (tid < 256) c_reg = c0[ub * HID + hc0 + uj];

    unsigned int bar_target = 0;
    if (tid == 0) bar_target = *((volatile unsigned int*)&g_bar_gen);
    __syncthreads();

    for (int t = 0; t < T_STEPS; t++) {
        // xp prefetch (DRAM latency overlaps staging)
        float xpi = 0, xpf = 0, xpg = 0, xpo = 0;
        if (tid < 256) {
            const float* xp = g_xproj + ((size_t)t * BATCH + ub) * GDIM + hc0 + uj;
            xpi = xp[0]; xpf = xp[HID]; xpg = xp[2 * HID]; xpo = xp[3 * HID];
        }
        const float* mrow = mask + t * BATCH;

        // ---- stage h (masked, split-bf16) into A smem ----
        if (t == 0) {
#pragma unroll
            for (int it = 0; it < 16; it++) {
                int idx = tid + it * NTHR;           // 0..8191 float4s
                int row = idx >> 7, f4 = idx & 127;  // k = f4*4
                float4 v = *(const float4*)(h0 + (size_t)row * HID + f4 * 4);
                float kp = 1.0f - __ldg(&mrow[row]);
                v.x *= kp; v.y *= kp; v.z *= kp; v.w *= kp;
                __nv_bfloat162 h01 = __float22bfloat162_rn(make_float2(v.x, v.y));
                __nv_bfloat162 h23 = __float22bfloat162_rn(make_float2(v.z, v.w));
                float2 f01 = __bfloat1622float2(h01);
                float2 f23 = __bfloat1622float2(h23);
                __nv_bfloat162 l01 = __float22bfloat162_rn(make_float2(v.x - f01.x, v.y - f01.y));
                __nv_bfloat162 l23 = __float22bfloat162_rn(make_float2(v.z - f23.x, v.w - f23.y));
                uint2 hv, lv;
                hv.x = *(uint32_t*)&h01; hv.y = *(uint32_t*)&h23;
                lv.x = *(uint32_t*)&l01; lv.y = *(uint32_t*)&l23;
                *(uint2*)(smraw + OFF_A + swz(row, f4 * 8))        = hv;
                *(uint2*)(smraw + OFF_A + swz(row, 1024 + f4 * 8)) = lv;
            }
        } else {
            const uint4* srchi = (const uint4*)g_hhi;
            const uint4* srclo = (const uint4*)g_hlo;
#pragma unroll
            for (int it = 0; it < 16; it++) {
                int idx = tid + it * NTHR;           // 0..8191: plane|row|c16
                int plane = idx >> 12;
                int row = (idx >> 6) & 63, c16 = idx & 63;
                uint4 v = plane ? srclo[(idx & 4095)] : srchi[(idx & 4095)];
                if (__ldg(&mrow[row]) != 0.0f) { v.x = v.y = v.z = v.w = 0u; }
                *(uint4*)(smraw + OFF_A + swz(row, plane * 1024 + c16 * 16)) = v;
            }
        }
        __syncthreads();

        // ---- MMA: 96 k-chunks of 16, one m16n8 tile per warp ----
        if (wid < 8) {
            float d0 = 0.f, d1 = 0.f, d2 = 0.f, d3 = 0.f;
#pragma unroll 4
            for (int kc = 0; kc < 96; kc++) {
                int kcA = (kc < 64) ? kc : kc - 64;   // A: hi,lo,hi
                int kcB = (kc < 32) ? kc : kc - 32;   // B: hi,hi,lo
                uint32_t aaddr = aRowBase + ((((uint32_t)kcA << 5) + aHi) ^ sA);
                uint32_t baddr = bRowBase + ((((uint32_t)kcB << 5) + bHi) ^ sB);
                uint32_t a0, a1, a2, a3, b0, b1;
                asm volatile("ldmatrix.sync.aligned.m8n8.x4.shared.b16 {%0,%1,%2,%3}, [%4];"
                             : "=r"(a0), "=r"(a1), "=r"(a2), "=r"(a3) : "r"(aaddr));
                asm volatile("ldmatrix.sync.aligned.m8n8.x2.shared.b16 {%0,%1}, [%2];"
                             : "=r"(b0), "=r"(b1) : "r"(baddr));
                asm volatile("mma.sync.aligned.m16n8k16.row.col.f32.bf16.bf16.f32 "
                             "{%0,%1,%2,%3}, {%4,%5,%6,%7}, {%8,%9}, {%0,%1,%2,%3};"
                             : "+f"(d0), "+f"(d1), "+f"(d2), "+f"(d3)
                             : "r"(a0), "r"(a1), "r"(a2), "r"(a3), "r"(b0), "r"(b1));
            }
            // write gates tile: rows mt*16+{r, r+8}, cols nt*8 + (lane&3)*2 + {0,1}
            int gr = mt * 16 + (lane >> 2);
            int gc = nt * 8 + (lane & 3) * 2;
            gates_s[gr * 17 + gc]           = d0;
            gates_s[gr * 17 + gc + 1]       = d1;
            gates_s[(gr + 8) * 17 + gc]     = d2;
            gates_s[(gr + 8) * 17 + gc + 1] = d3;
        }
        __syncthreads();

        // ---- LSTM cell update (threads 0..255) ----
        if (tid < 256) {
            float kp = 1.0f - __ldg(&mrow[ub]);
            float gi = gates_s[ub * 17 + 0  + uj] + xpi;
            float gf = gates_s[ub * 17 + 4  + uj] + xpf;
            float gg = gates_s[ub * 17 + 8  + uj] + xpg;
            float go = gates_s[ub * 17 + 12 + uj] + xpo;
            float cprev = c_reg * kp;
            float cn = sigmoidf_(gf) * cprev + sigmoidf_(gi) * tanhf(gg);
            float hn = sigmoidf_(go) * tanhf(cn);
            c_reg = cn;
            h_last = hn;
            int hcol = hc0 + uj;
            out[(size_t)t * BATCH * HID + ub * HID + hcol] = hn;
            __nv_bfloat16 hh = __float2bfloat16_rn(hn);
            g_hhi[ub * HID + hcol] = hh;
            g_hlo[ub * HID + hcol] = __float2bfloat16_rn(hn - __bfloat162float(hh));
        }

        // ---- software grid barrier ----
        __syncthreads();
        if (tid == 0) {
            asm volatile("fence.acq_rel.gpu;" ::: "memory");
            bar_target += 1;
            unsigned int old = atomicAdd(&g_bar_count, 1);
            if (old == NCTA - 1) {
                atomicExch(&g_bar_count, 0);
                atomicAdd(&g_bar_gen, 1);
            } else {
                while ((int)(*((volatile unsigned int*)&g_bar_gen) - bar_target) < 0)
                    __nanosleep(32);
            }
            asm volatile("fence.acq_rel.gpu;" ::: "memory");
        }
        __syncthreads();
    }

    // Finals
    if (tid < 256) {
        float* hfin = out + (size_t)T_STEPS * BATCH * HID;
        float* cfin = hfin + BATCH * HID;
        hfin[ub * HID + hc0 + uj] = h_last;
        cfin[ub * HID + hc0 + uj] = c_reg;
    }
}

// =====================================================================
extern "C" void kernel_launch(void* const* d_in, const int* in_sizes, int n_in,
                              void* d_out, int out_size) {
    (void)in_sizes; (void)n_in; (void)out_size;
    const float* x    = (const float*)d_in[0];
    const float* h0   = (const float*)d_in[1];
    const float* c0   = (const float*)d_in[2];
    const float* mask = (const float*)d_in[3];
    const float* Wx   = (const float*)d_in[4];
    const float* Wh   = (const float*)d_in[5];
    const float* b    = (const float*)d_in[6];
    float* out = (float*)d_out;

    dim3 g1(GDIM / BN, (T_STEPS * BATCH) / BM);
    k_xproj<<<g1, 256>>>(x, Wx, b);

    cudaFuncSetAttribute(k_rnn, cudaFuncAttributeMaxDynamicSharedMemorySize, SMEM2);
    k_rnn<<<NCTA, NTHR, SMEM2>>>(h0, c0, mask, Wh, out);
}

// round 7
// speedup vs baseline: 2.0198x; 1.2796x over previous
#include <cuda_runtime.h>
#include <cuda_bf16.h>
#include <math.h>
#include <stdint.h>

// Problem constants (fixed by setup_inputs)
#define T_STEPS 512
#define BATCH   64
#define HID     512
#define GDIM    2048   // 4*H
#define DDIM    512
#define MROWS   (T_STEPS * BATCH)   // 32768

typedef unsigned long long ull;

// ---- scratch (device globals: allocation-free rule) ----
__device__ float g_xproj[(size_t)MROWS * GDIM];                 // 268 MB
__device__ __align__(16) __nv_bfloat16 g_xhi[(size_t)MROWS * DDIM];  // 33.5 MB
__device__ __align__(16) __nv_bfloat16 g_xlo[(size_t)MROWS * DDIM];
__device__ __align__(16) __nv_bfloat16 g_wthi[(size_t)GDIM * DDIM];  // 2 MB (transposed)
__device__ __align__(16) __nv_bfloat16 g_wtlo[(size_t)GDIM * DDIM];
__device__ __align__(16) __nv_bfloat16 g_hhi[BATCH * HID];
__device__ __align__(16) __nv_bfloat16 g_hlo[BATCH * HID];
__device__ unsigned int g_bar_count = 0;
__device__ unsigned int g_bar_gen   = 0;

__device__ __forceinline__ float sigmoidf_(float x) { return 1.0f / (1.0f + expf(-x)); }

__device__ __forceinline__ uint32_t smem_u32(const void* p) {
    uint32_t a;
    asm("{ .reg .u64 t; cvta.to.shared.u64 t, %1; cvt.u32.u64 %0, t; }" : "=r"(a) : "l"(p));
    return a;
}

#define CP_ASYNC16(dst, src) \
    asm volatile("cp.async.cg.shared.global [%0], [%1], 16;" :: "r"(dst), "l"(src))
#define CP_COMMIT()   asm volatile("cp.async.commit_group;" ::: "memory")
#define CP_WAIT(n)    asm volatile("cp.async.wait_group %0;" :: "n"(n) : "memory")

#define LDSM_X4(r0, r1, r2, r3, a) \
    asm volatile("ldmatrix.sync.aligned.m8n8.x4.shared.b16 {%0,%1,%2,%3}, [%4];" \
                 : "=r"(r0), "=r"(r1), "=r"(r2), "=r"(r3) : "r"(a))
#define LDSM_X2(r0, r1, a) \
    asm volatile("ldmatrix.sync.aligned.m8n8.x2.shared.b16 {%0,%1}, [%2];" \
                 : "=r"(r0), "=r"(r1) : "r"(a))
#define MMA16816(d, a, b0, b1) \
    asm volatile("mma.sync.aligned.m16n8k16.row.col.f32.bf16.bf16.f32 " \
                 "{%0,%1,%2,%3}, {%4,%5,%6,%7}, {%8,%9}, {%0,%1,%2,%3};" \
                 : "+f"((d)[0]), "+f"((d)[1]), "+f"((d)[2]), "+f"((d)[3]) \
                 : "r"((a)[0]), "r"((a)[1]), "r"((a)[2]), "r"((a)[3]), "r"(b0), "r"(b1))

// =====================================================================
// k_convert_x: split x (fp32) into bf16 hi/lo planes.
// =====================================================================
__global__ __launch_bounds__(256) void k_convert_x(const float* __restrict__ x) {
    size_t i = (size_t)blockIdx.x * 256 + threadIdx.x;   // float4 index, 4.19M total
    float4 v = ((const float4*)x)[i];
    __nv_bfloat162 h01 = __float22bfloat162_rn(make_float2(v.x, v.y));
    __nv_bfloat162 h23 = __float22bfloat162_rn(make_float2(v.z, v.w));
    float2 f01 = __bfloat1622float2(h01);
    float2 f23 = __bfloat1622float2(h23);
    __nv_bfloat162 l01 = __float22bfloat162_rn(make_float2(v.x - f01.x, v.y - f01.y));
    __nv_bfloat162 l23 = __float22bfloat162_rn(make_float2(v.z - f23.x, v.w - f23.y));
    uint2 hv, lv;
    hv.x = *(uint32_t*)&h01; hv.y = *(uint32_t*)&h23;
    lv.x = *(uint32_t*)&l01; lv.y = *(uint32_t*)&l23;
    ((uint2*)g_xhi)[i] = hv;
    ((uint2*)g_xlo)[i] = lv;
}

// =====================================================================
// k_convert_w: transpose Wx [512][2048] -> [2048][512] + split bf16.
// 32x32 smem tiles, 256 threads.
// =====================================================================
__global__ __launch_bounds__(256) void k_convert_w(const float* __restrict__ Wx) {
    __shared__ float tile[32][33];
    const int n0 = blockIdx.x * 32;   // 64 blocks
    const int k0 = blockIdx.y * 32;   // 16 blocks
    const int c = threadIdx.x & 31, r = threadIdx.x >> 5;
#pragma unroll
    for (int i = 0; i < 4; i++)
        tile[r + i * 8][c] = Wx[(size_t)(k0 + r + i * 8) * GDIM + n0 + c];
    __syncthreads();
#pragma unroll
    for (int i = 0; i < 4; i++) {
        int nn = r + i * 8;
        float v = tile[c][nn];
        __nv_bfloat16 hi = __float2bfloat16_rn(v);
        g_wthi[(size_t)(n0 + nn) * DDIM + k0 + c] = hi;
        g_wtlo[(size_t)(n0 + nn) * DDIM + k0 + c] =
            __float2bfloat16_rn(v - __bfloat162float(hi));
    }
}

// =====================================================================
// k_xproj_hmma: x_proj[M,2048] = x @ Wx + b via split-bf16 HMMA.
// BM=128, BN=128, BK=32, double-buffered cp.async. 8 warps, warp m32n64.
// 3 terms: hi*hi + lo*hi + hi*lo.
// =====================================================================
#define XSTAGE 32768   // A 16KB + B 16KB
#define XSMEM  (2 * XSTAGE)

__global__ __launch_bounds__(256, 2) void k_xproj_hmma(const float* __restrict__ bias) {
    extern __shared__ char xsm[];
    const uint32_t smb = smem_u32(xsm);
    const int tid = threadIdx.x, lane = tid & 31, wid = tid >> 5;
    const int n0 = blockIdx.x * 128;
    const int m0 = blockIdx.y * 128;
    const int wm = wid & 3, wn = wid >> 2;

    // staging coords: row r (0..127), 4 units of one plane per thread
    const int sr = tid >> 1;
    const int spl = tid & 1;                      // 0 = hi, 1 = lo
    const uint32_t sdst0 = (uint32_t)(sr * 128);  // row base (bytes)
    const int sswz = sr & 7;

    float acc[2][8][4];
#pragma unroll
    for (int mi = 0; mi < 2; mi++)
#pragma unroll
        for (int g = 0; g < 8; g++)
#pragma unroll
            for (int q = 0; q < 4; q++) acc[mi][g][q] = 0.0f;

    const __nv_bfloat16* asrc = (spl ? g_xlo : g_xhi) + (size_t)(m0 + sr) * DDIM;
    const __nv_bfloat16* bsrc = (spl ? g_wtlo : g_wthi) + (size_t)(n0 + sr) * DDIM;

    // prefetch stage 0
#pragma unroll
    for (int jj = 0; jj < 4; jj++) {
        int j = spl * 4 + jj;
        uint32_t dA = smb + sdst0 + (uint32_t)((j ^ sswz) << 4);
        CP_ASYNC16(dA, asrc + jj * 8);
        CP_ASYNC16(dA + 16384, bsrc + jj * 8);
    }
    CP_COMMIT();

    for (int s = 0; s < 16; s++) {
        if (s < 15) {
            int k0 = (s + 1) * 32;
            uint32_t bufn = ((uint32_t)(s + 1) & 1) * XSTAGE;
#pragma unroll
            for (int jj = 0; jj < 4; jj++) {
                int j = spl * 4 + jj;
                uint32_t dA = smb + bufn + sdst0 + (uint32_t)((j ^ sswz) << 4);
                CP_ASYNC16(dA, asrc + k0 + jj * 8);
                CP_ASYNC16(dA + 16384, bsrc + k0 + jj * 8);
            }
            CP_COMMIT();
            CP_WAIT(1);
        } else {
            CP_WAIT(0);
        }
        __syncthreads();

        const uint32_t Ab = smb + ((uint32_t)s & 1) * XSTAGE;
        const uint32_t Bb = Ab + 16384;
#pragma unroll
        for (int kk = 0; kk < 2; kk++) {       // two k16 chunks per stage
            uint32_t ah[2][4], al[2][4];
#pragma unroll
            for (int mi = 0; mi < 2; mi++) {
                int ar = wm * 32 + mi * 16 + (lane & 15);
                int uh = kk * 2 + ((lane >> 4) & 1);
                uint32_t base = Ab + (uint32_t)(ar * 128);
                int s7 = ar & 7;
                LDSM_X4(ah[mi][0], ah[mi][1], ah[mi][2], ah[mi][3],
                        base + (uint32_t)((uh ^ s7) << 4));
                LDSM_X4(al[mi][0], al[mi][1], al[mi][2], al[mi][3],
                        base + (uint32_t)(((uh + 4) ^ s7) << 4));
            }
#pragma unroll
            for (int g = 0; g < 8; g++) {
                int br = wn * 64 + g * 8 + (lane & 7);
                int ub = kk * 2 + ((lane >> 3) & 1);
                uint32_t base = Bb + (uint32_t)(br * 128);
                int s7 = br & 7;
                uint32_t b0, b1, c0, c1;
                LDSM_X2(b0, b1, base + (uint32_t)((ub ^ s7) << 4));
                LDSM_X2(c0, c1, base + (uint32_t)(((ub + 4) ^ s7) << 4));
#pragma unroll
                for (int mi = 0; mi < 2; mi++) {
                    MMA16816(acc[mi][g], ah[mi], b0, b1);
                    MMA16816(acc[mi][g], al[mi], b0, b1);
                    MMA16816(acc[mi][g], ah[mi], c0, c1);
                }
            }
        }
        __syncthreads();
    }

    // epilogue: + bias, store fp32
#pragma unroll
    for (int mi = 0; mi < 2; mi++) {
        int gr = m0 + wm * 32 + mi * 16 + (lane >> 2);
#pragma unroll
        for (int g = 0; g < 8; g++) {
            int gc = n0 + wn * 64 + g * 8 + (lane & 3) * 2;
            float2 bb = *(const float2*)(bias + gc);
            float2 v0 = {acc[mi][g][0] + bb.x, acc[mi][g][1] + bb.y};
            float2 v1 = {acc[mi][g][2] + bb.x, acc[mi][g][3] + bb.y};
            *(float2*)(g_xproj + (size_t)gr * GDIM + gc)       = v0;
            *(float2*)(g_xproj + (size_t)(gr + 8) * GDIM + gc) = v1;
        }
    }
}

// =====================================================================
// k_rnn: persistent masked-LSTM recurrence on HMMA (round-6 core).
// Changes: cp.async staging, 3-term MMA loops, release/acquire barrier.
// =====================================================================
#define NCTA 128
#define NTHR 512

#define OFF_A  0        // 64 rows x 2048B = 131072
#define OFF_B  131072   // 16 rows x 2048B = 32768
#define OFF_G  163840   // gates 64 x 17 floats = 4352
#define SMEM2  168448

__device__ __forceinline__ uint32_t swz(int row, int kbyte) {
    return (uint32_t)(row * 2048) + ((((uint32_t)kbyte >> 4) ^ (uint32_t)(row & 7)) << 4)
         + ((uint32_t)kbyte & 15u);
}

__global__ __launch_bounds__(NTHR, 1) void k_rnn(const float* __restrict__ h0,
                                                 const float* __restrict__ c0,
                                                 const float* __restrict__ mask,
                                                 const float* __restrict__ Wh,
                                                 float* __restrict__ out) {
    extern __shared__ char smraw[];
    const uint32_t smb = smem_u32(smraw);
    float* gates_s = (float*)(smraw + OFF_G);
    const int tid = threadIdx.x, lane = tid & 31, wid = tid >> 5;
    const int cta = blockIdx.x, hc0 = cta * 4;

    // ---- Wh slice -> B smem, split-bf16 (hi at kbyte<1024, lo >=1024) ----
#pragma unroll 4
    for (int it = 0; it < 32; it++) {
        int e = tid + it * NTHR;
        int n = e >> 10, k = e & 1023;
        int gcol = (n >> 2) * HID + hc0 + (n & 3);
        float v = Wh[(size_t)(k & 511) * GDIM + gcol];
        __nv_bfloat16 hi = __float2bfloat16_rn(v);
        __nv_bfloat16 bv = (k < 512) ? hi : __float2bfloat16_rn(v - __bfloat162float(hi));
        *(__nv_bfloat16*)(smraw + OFF_B + swz(n, k * 2)) = bv;
    }

    // MMA warp coords (wid < 8)
    const int mt = wid & 3, nt = wid >> 2;
    const int ar = mt * 16 + (lane & 15);
    const uint32_t aRowBase = smb + OFF_A + (uint32_t)ar * 2048;
    const uint32_t sA = (uint32_t)(ar & 7) << 4;
    const uint32_t aHi = (uint32_t)((lane >> 4) & 1) << 4;
    const int br = nt * 8 + (lane & 7);
    const uint32_t bRowBase = smb + OFF_B + (uint32_t)br * 2048;
    const uint32_t sB = (uint32_t)(br & 7) << 4;
    const uint32_t bHi = (uint32_t)((lane >> 3) & 1) << 4;

    // staging coords: one row per 8 threads, 16 x 16B units each (linear)
    const int strow = tid >> 3;
    const int stj   = tid & 7;
    const uint32_t stdst0 = smb + OFF_A + (uint32_t)(strow * 2048)
                          + ((uint32_t)(stj ^ (strow & 7)) << 4);
    const __nv_bfloat16* sthi = g_hhi + strow * HID + stj * 8;
    const __nv_bfloat16* stlo = g_hlo + strow * HID + stj * 8;

    // update mapping (first 256 threads)
    const int ub = tid >> 2;
    const int uj = tid & 3;
    float c_reg = 0.0f, h_last = 0.0f;
    if (tid < 256) c_reg = c0[ub * HID + hc0 + uj];

    unsigned int bar_target = 0;
    if (tid == 0) bar_target = *((volatile unsigned int*)&g_bar_gen);
    __syncthreads();

    for (int t = 0; t < T_STEPS; t++) {
        // xp prefetch (DRAM latency overlaps staging)
        float xpi = 0, xpf = 0, xpg = 0, xpo = 0;
        if (tid < 256) {
            const float* xp = g_xproj + ((size_t)t * BATCH + ub) * GDIM + hc0 + uj;
            xpi = xp[0]; xpf = xp[HID]; xpg = xp[2 * HID]; xpo = xp[3 * HID];
        }
        const float* mrow = mask + t * BATCH;

        // ---- stage h into A smem ----
        if (t == 0) {
#pragma unroll
            for (int it = 0; it < 16; it++) {
                int idx = tid + it * NTHR;
                int row = idx >> 7, f4 = idx & 127;
                float4 v = *(const float4*)(h0 + (size_t)row * HID + f4 * 4);
                float kp = 1.0f - __ldg(&mrow[row]);
                v.x *= kp; v.y *= kp; v.z *= kp; v.w *= kp;
                __nv_bfloat162 h01 = __float22bfloat162_rn(make_float2(v.x, v.y));
                __nv_bfloat162 h23 = __float22bfloat162_rn(make_float2(v.z, v.w));
                float2 f01 = __bfloat1622float2(h01);
                float2 f23 = __bfloat1622float2(h23);
                __nv_bfloat162 l01 = __float22bfloat162_rn(make_float2(v.x - f01.x, v.y - f01.y));
                __nv_bfloat162 l23 = __float22bfloat162_rn(make_float2(v.z - f23.x, v.w - f23.y));
                uint2 hv, lv;
                hv.x = *(uint32_t*)&h01; hv.y = *(uint32_t*)&h23;
                lv.x = *(uint32_t*)&l01; lv.y = *(uint32_t*)&l23;
                *(uint2*)(smraw + OFF_A + swz(row, f4 * 8))        = hv;
                *(uint2*)(smraw + OFF_A + swz(row, 1024 + f4 * 8)) = lv;
            }
        } else {
            float mval = __ldg(&mrow[strow]);
            uint32_t d = stdst0;
#pragma unroll
            for (int i = 0; i < 8; i++) { CP_ASYNC16(d, sthi + i * 64); d += 128; }
#pragma unroll
            for (int i = 0; i < 8; i++) { CP_ASYNC16(d, stlo + i * 64); d += 128; }
            CP_COMMIT();
            CP_WAIT(0);
            if (mval != 0.0f) {
                uint4 z = {0u, 0u, 0u, 0u};
                uint32_t dz = stdst0;
#pragma unroll
                for (int i = 0; i < 16; i++) {
                    asm volatile("st.shared.v4.b32 [%0], {%1,%2,%3,%4};"
                                 :: "r"(dz), "r"(z.x), "r"(z.y), "r"(z.z), "r"(z.w));
                    dz += 128;
                }
            }
        }
        __syncthreads();

        // ---- MMA: 3 terms x 32 k-chunks, one m16n8 tile per warp ----
        if (wid < 8) {
            float d[4] = {0.f, 0.f, 0.f, 0.f};
#pragma unroll
            for (int term = 0; term < 3; term++) {
                const uint32_t aOff = (term == 1) ? 1024u : 0u;
                const uint32_t bOff = (term == 2) ? 1024u : 0u;
#pragma unroll 8
                for (int kc = 0; kc < 32; kc++) {
                    uint32_t kb = (uint32_t)kc << 5;
                    uint32_t aaddr = aRowBase + ((aOff + kb + aHi) ^ sA);
                    uint32_t baddr = bRowBase + ((bOff + kb + bHi) ^ sB);
                    uint32_t a[4], b0, b1;
                    LDSM_X4(a[0], a[1], a[2], a[3], aaddr);
                    LDSM_X2(b0, b1, baddr);
                    MMA16816(d, a, b0, b1);
                }
            }
            int gr = mt * 16 + (lane >> 2);
            int gc = nt * 8 + (lane & 3) * 2;
            gates_s[gr * 17 + gc]           = d[0];
            gates_s[gr * 17 + gc + 1]       = d[1];
            gates_s[(gr + 8) * 17 + gc]     = d[2];
            gates_s[(gr + 8) * 17 + gc + 1] = d[3];
        }
        __syncthreads();

        // ---- LSTM cell update (threads 0..255) ----
        if (tid < 256) {
            float kp = 1.0f - __ldg(&mrow[ub]);
            float gi = gates_s[ub * 17 + 0  + uj] + xpi;
            float gf = gates_s[ub * 17 + 4  + uj] + xpf;
            float gg = gates_s[ub * 17 + 8  + uj] + xpg;
            float go = gates_s[ub * 17 + 12 + uj] + xpo;
            float cprev = c_reg * kp;
            float cn = sigmoidf_(gf) * cprev + sigmoidf_(gi) * tanhf(gg);
            float hn = sigmoidf_(go) * tanhf(cn);
            c_reg = cn;
            h_last = hn;
            int hcol = hc0 + uj;
            out[(size_t)t * BATCH * HID + ub * HID + hcol] = hn;
            __nv_bfloat16 hh = __float2bfloat16_rn(hn);
            g_hhi[ub * HID + hcol] = hh;
            g_hlo[ub * HID + hcol] = __float2bfloat16_rn(hn - __bfloat162float(hh));
        }

        // ---- grid barrier: release/acquire atomics (no full fences) ----
        __syncthreads();
        if (tid == 0) {
            bar_target += 1;
            unsigned int old;
            asm volatile("atom.add.acq_rel.gpu.u32 %0, [%1], 1;"
                         : "=r"(old) : "l"(&g_bar_count) : "memory");
            if (old == NCTA - 1) {
                asm volatile("st.relaxed.gpu.u32 [%0], 0;" :: "l"(&g_bar_count) : "memory");
                asm volatile("red.add.release.gpu.u32 [%0], 1;" :: "l"(&g_bar_gen) : "memory");
            } else {
                unsigned int g;
                while (1) {
                    asm volatile("ld.acquire.gpu.u32 %0, [%1];"
                                 : "=r"(g) : "l"(&g_bar_gen) : "memory");
                    if ((int)(g - bar_target) >= 0) break;
                    __nanosleep(20);
                }
            }
        }
        __syncthreads();
    }

    // Finals
    if (tid < 256) {
        float* hfin = out + (size_t)T_STEPS * BATCH * HID;
        float* cfin = hfin + BATCH * HID;
        hfin[ub * HID + hc0 + uj] = h_last;
        cfin[ub * HID + hc0 + uj] = c_reg;
    }
}

// =====================================================================
extern "C" void kernel_launch(void* const* d_in, const int* in_sizes, int n_in,
                              void* d_out, int out_size) {
    (void)in_sizes; (void)n_in; (void)out_size;
    const float* x    = (const float*)d_in[0];
    const float* h0   = (const float*)d_in[1];
    const float* c0   = (const float*)d_in[2];
    const float* mask = (const float*)d_in[3];
    const float* Wx   = (const float*)d_in[4];
    const float* Wh   = (const float*)d_in[5];
    const float* b    = (const float*)d_in[6];
    float* out = (float*)d_out;

    // converts (off critical path, ~50us)
    k_convert_x<<<MROWS * DDIM / 4 / 256, 256>>>(x);
    k_convert_w<<<dim3(GDIM / 32, DDIM / 32), 256>>>(Wx);

    // input projection on HMMA
    cudaFuncSetAttribute(k_xproj_hmma, cudaFuncAttributeMaxDynamicSharedMemorySize, XSMEM);
    k_xproj_hmma<<<dim3(GDIM / 128, MROWS / 128), 256, XSMEM>>>(b);

    // persistent recurrence
    cudaFuncSetAttribute(k_rnn, cudaFuncAttributeMaxDynamicSharedMemorySize, SMEM2);
    k_rnn<<<NCTA, NTHR, SMEM2>>>(h0, c0, mask, Wh, out);
}